// round 5
// baseline (speedup 1.0000x reference)
#include <cuda_runtime.h>

#define B_   4
#define C_   64
#define O_   64
#define H_   128
#define W_   128
#define KK   9
#define HW_  (H_ * W_)

// ---------------- device scratch (allocation-free rule) ----------------
__device__ float2 g_x2[B_ * C_ * HW_];     // paired x: (x[y][x], x[y][x+1])
__device__ float  g_wB[KK * 8192];         // per tap: B frags, hi[4096] then lo[4096]

__device__ __forceinline__ unsigned f2tf32(float f) {
    unsigned r; asm("cvt.rna.tf32.f32 %0, %1;" : "=r"(r) : "f"(f)); return r;
}

// mma.sync m16n8k8 tf32 (sm_80 ISA -> valid on base sm_103 target)
#define MMA(d, a0, a1, a2, a3, b0, b1)                                   \
    asm volatile("mma.sync.aligned.m16n8k8.row.col.f32.tf32.tf32.f32 "   \
        "{%0,%1,%2,%3}, {%4,%5,%6,%7}, {%8,%9}, {%0,%1,%2,%3};"          \
        : "+f"((d)[0]), "+f"((d)[1]), "+f"((d)[2]), "+f"((d)[3])         \
        : "r"(a0), "r"(a1), "r"(a2), "r"(a3), "r"(b0), "r"(b1))

// named barriers: 1+s = "stage s full", 3+s = "stage s empty"; count = 384
#define BSYNC(id)   asm volatile("bar.sync %0, 384;"   :: "r"(id) : "memory")
#define BARRIVE(id) asm volatile("bar.arrive %0, 384;" :: "r"(id) : "memory")

// ---------------- prep kernels ----------------
// B fragment layout per tap: [kt(8)][nt(8)][lane(32)][j(2)] floats, hi then lo.
// lane l holds b0=(k=tg, n=g), b1=(k=tg+4, n=g) with g=l>>2, tg=l&3.
__global__ void prep_w(const float* __restrict__ w) {
    int i = blockIdx.x * 256 + threadIdx.x;           // over O*C*KK = 36864
    if (i < O_ * C_ * KK) {
        int o = i / (C_ * KK);
        int r = i - o * (C_ * KK);
        int c = r / KK;
        int k = r - c * KK;
        float v = w[i];
        unsigned hib = f2tf32(v);
        float hif = __uint_as_float(hib);
        unsigned lob = f2tf32(v - hif);
        int kt = c >> 3, tg = c & 3, kh = (c >> 2) & 1;
        int nt = o >> 3, g = o & 7;
        int l = 4 * g + tg;
        int idx = k * 8192 + ((kt * 8 + nt) * 32 + l) * 2 + kh;
        g_wB[idx]        = hif;
        g_wB[idx + 4096] = __uint_as_float(lob);
    }
}

__global__ void prep_x2(const float* __restrict__ x) {
    int i = blockIdx.x * 256 + threadIdx.x;           // over B*C*HW
    if (i < B_ * C_ * HW_) {
        int col = i & (W_ - 1);
        float a = x[i];
        float b = (col < W_ - 1) ? x[i + 1] : a;      // clamp; weight is 0 there
        g_x2[i] = make_float2(a, b);
    }
}

// ---------------- main kernel ----------------
// smem (bytes):  A hi/lo double-buffered + B hi/lo double-buffered
//  AH(s) = 1024 + s*65536 (32KB), AL(s) = AH(s)+32768
//  BB(s) = 132096 + s*32768 (hi 16KB, lo 16KB)
#define AH(s) (1024u + (unsigned)(s) * 65536u)
#define AL(s) (AH(s) + 32768u)
#define BB(s) (132096u + (unsigned)(s) * 32768u)
#define SMEM_TOTAL 197632

__global__ __launch_bounds__(384, 1)
void dconv_main(const float* __restrict__ offset,
                const float* __restrict__ bias,
                float* __restrict__ out) {
    extern __shared__ char smc[];

    const int tid   = threadIdx.x;
    const int batch = blockIdx.x >> 7;
    const int ho    = blockIdx.x & 127;

    if (tid < 256) {
        // ================= PRODUCERS (warps 0-7) =================
        const int p     = tid & 127;         // pixel in row
        const int chalf = tid >> 7;          // channel half (0/1), 32 c each
        const int g  = p & 7;
        const int rh = (p >> 3) & 1;
        const int mt = p >> 4;

        const float2* xb2  = g_x2 + (batch * C_ + chalf * 32) * HW_;
        const float*  offb = offset + (batch * 2 * KK) * HW_ + ho * W_ + p;

        float offy[KK], offx[KK];
        #pragma unroll
        for (int k = 0; k < KK; k++) {
            offy[k] = __ldg(offb + (2 * k) * HW_);
            offx[k] = __ldg(offb + (2 * k + 1) * HW_);
        }

        for (int k = 0; k < KK; k++) {
            const int s = k & 1;
            if (k >= 2) BSYNC(3 + s);        // wait stage empty

            // stage this tap's B fragments (hi+lo, 32KB straight copy)
            {
                const float4* src = (const float4*)(g_wB + k * 8192);
                float4* dst = (float4*)(smc + BB(s));
                #pragma unroll
                for (int j = 0; j < 8; j++) dst[tid + j * 256] = src[tid + j * 256];
            }

            // bilinear corner math (once per pixel/tap) -- proven in R3
            const int ki = k / 3, kj = k - ki * 3;
            const float py  = offy[k] + (float)(ki - 1 + ho);
            const float pxx = offx[k] + (float)(kj - 1 + p);
            const float y0f = floorf(py), x0f = floorf(pxx);
            const float ly = py - y0f,  lx = pxx - x0f;
            const float hy = 1.f - ly,  hx = 1.f - lx;
            const int y0 = (int)y0f, x0 = (int)x0f;

            const float wy0 = (y0 >= 0  && y0 < H_)     ? hy : 0.f;
            const float wy1 = (y0 >= -1 && y0 < H_ - 1) ? ly : 0.f;
            const int ry0 = min(max(y0, 0), H_ - 1);
            const int ry1 = min(max(y0 + 1, 0), H_ - 1);

            float wa, wb;
            if (x0 >= 0 && x0 < W_) { wa = hx; wb = (x0 < W_ - 1) ? lx : 0.f; }
            else if (x0 == -1)      { wa = lx; wb = 0.f; }
            else                    { wa = 0.f; wb = 0.f; }
            const int bx = min(max(x0, 0), W_ - 1);

            const float u0 = wy0 * wa, u1 = wy0 * wb;
            const float u2 = wy1 * wa, u3 = wy1 * wb;

            const float2* p0 = xb2 + ry0 * W_ + bx;
            const float2* p1 = xb2 + ry1 * W_ + bx;

            char* Ah = smc + AH(s);
            char* Al = smc + AL(s);

            // A fragment store: block (mt, kt_global) of 512B; slot = g + 8*tg;
            // word i' = 2*rh + kh  ->  thread writes one uint2 per (kt,tg)
            #pragma unroll
            for (int ktl = 0; ktl < 4; ktl++) {
                #pragma unroll
                for (int tg = 0; tg < 4; tg++) {
                    const int cl0 = ktl * 8 + tg;        // kh = 0
                    const int cl1 = cl0 + 4;             // kh = 1
                    const float2 a0 = __ldg(p0 + cl0 * HW_);
                    const float2 b0 = __ldg(p1 + cl0 * HW_);
                    const float2 a1 = __ldg(p0 + cl1 * HW_);
                    const float2 b1 = __ldg(p1 + cl1 * HW_);
                    const float v0 = u0 * a0.x + u1 * a0.y + u2 * b0.x + u3 * b0.y;
                    const float v1 = u0 * a1.x + u1 * a1.y + u2 * b1.x + u3 * b1.y;

                    const unsigned h0 = f2tf32(v0);
                    const unsigned l0 = f2tf32(v0 - __uint_as_float(h0));
                    const unsigned h1 = f2tf32(v1);
                    const unsigned l1 = f2tf32(v1 - __uint_as_float(h1));

                    const unsigned off =
                        (unsigned)((((mt * 8 + chalf * 4 + ktl) * 32) +
                                    (g + 8 * tg)) * 16 + rh * 8);
                    *(uint2*)(Ah + off) = make_uint2(h0, h1);
                    *(uint2*)(Al + off) = make_uint2(l0, l1);
                }
            }

            BARRIVE(1 + s);                  // stage full
        }
    } else {
        // ================= CONSUMERS (warps 8-11, one per SMSP) =================
        const int wc   = (tid >> 5) - 8;     // 0..3
        const int wm   = wc >> 1;            // m-half  (m64)
        const int wn   = wc & 1;             // n-half  (n32)
        const int lane = tid & 31;
        const int sl   = (lane >> 2) | ((lane & 3) << 3);   // A slot swizzle

        float D[4][4][4];
        #pragma unroll
        for (int i = 0; i < 4; i++)
            #pragma unroll
            for (int j = 0; j < 4; j++)
                #pragma unroll
                for (int q = 0; q < 4; q++) D[i][j][q] = 0.f;

        for (int k = 0; k < KK; k++) {
            const int s = k & 1;
            BSYNC(1 + s);                    // wait stage full

            const char* Ah = smc + AH(s);
            const char* Al = smc + AL(s);
            const char* Bh = smc + BB(s);
            const char* Bl = Bh + 16384;

            for (int kt = 0; kt < 8; kt++) {
                uint2 bh[4], bl[4];
                #pragma unroll
                for (int nt = 0; nt < 4; nt++) {
                    const unsigned boff =
                        (unsigned)(((kt * 8 + wn * 4 + nt) * 32 + lane) * 8);
                    bh[nt] = *(const uint2*)(Bh + boff);
                    bl[nt] = *(const uint2*)(Bl + boff);
                }
                uint4 ah[4], al[4];
                #pragma unroll
                for (int mt = 0; mt < 4; mt++) {
                    const unsigned aoff =
                        (unsigned)((((wm * 4 + mt) * 8 + kt) * 32 + sl) * 16);
                    ah[mt] = *(const uint4*)(Ah + aoff);
                    al[mt] = *(const uint4*)(Al + aoff);
                }
                #pragma unroll
                for (int mt = 0; mt < 4; mt++) {
                    // reg order in smem: [i'] = {(rh0,kh0),(rh0,kh1),(rh1,kh0),(rh1,kh1)}
                    // mma wants a0=(g,tg) a1=(g+8,tg) a2=(g,tg+4) a3=(g+8,tg+4)
                    const unsigned A0 = ah[mt].x, A1 = ah[mt].z,
                                   A2 = ah[mt].y, A3 = ah[mt].w;
                    const unsigned L0 = al[mt].x, L1 = al[mt].z,
                                   L2 = al[mt].y, L3 = al[mt].w;
                    #pragma unroll
                    for (int nt = 0; nt < 4; nt++) {
                        MMA(D[mt][nt], A0, A1, A2, A3, bh[nt].x, bh[nt].y); // Ah*Bh
                        MMA(D[mt][nt], L0, L1, L2, L3, bh[nt].x, bh[nt].y); // Al*Bh
                        MMA(D[mt][nt], A0, A1, A2, A3, bl[nt].x, bl[nt].y); // Ah*Bl
                    }
                }
            }

            BARRIVE(3 + s);                  // stage empty
        }

        // ---------------- epilogue ----------------
        const int gg = lane >> 2, tg = lane & 3;
        #pragma unroll
        for (int nt = 0; nt < 4; nt++) {
            const int o = wn * 32 + nt * 8 + 2 * tg;
            const float b0 = __ldg(bias + o);
            const float b1 = __ldg(bias + o + 1);
            float* op = out + (batch * O_ + o) * HW_ + ho * W_;
            #pragma unroll
            for (int mt = 0; mt < 4; mt++) {
                const int px = wm * 64 + mt * 16 + gg;
                op[px]            = D[mt][nt][0] + b0;
                op[HW_ + px]      = D[mt][nt][1] + b1;
                op[px + 8]        = D[mt][nt][2] + b0;
                op[HW_ + px + 8]  = D[mt][nt][3] + b1;
            }
        }
    }
}

extern "C" void kernel_launch(void* const* d_in, const int* in_sizes, int n_in,
                              void* d_out, int out_size) {
    const float* x      = (const float*)d_in[0];
    const float* offset = (const float*)d_in[1];
    const float* weight = (const float*)d_in[2];
    const float* bias   = (const float*)d_in[3];
    float* out = (float*)d_out;

    cudaFuncSetAttribute(dconv_main,
                         cudaFuncAttributeMaxDynamicSharedMemorySize, SMEM_TOTAL);

    prep_w<<<(O_ * C_ * KK + 255) / 256, 256>>>(weight);
    prep_x2<<<(B_ * C_ * HW_ + 255) / 256, 256>>>(x);
    dconv_main<<<B_ * H_, 384, SMEM_TOTAL>>>(offset, bias, out);
}

// round 7
// speedup vs baseline: 1.3018x; 1.3018x over previous
#include <cuda_runtime.h>

#define B_   4
#define C_   64
#define O_   64
#define H_   128
#define W_   128
#define KK   9
#define HW_  (H_ * W_)

// ---------------- device scratch (allocation-free rule) ----------------
__device__ float4 g_x4[B_ * C_ * HW_];   // (x[y][x], x[y][x+1], x[y+1][x], x[y+1][x+1])
__device__ float  g_wT[KK * C_ * O_];    // weights [k][c][o]

// ---------------- prep kernels ----------------
__global__ void prep_w(const float* __restrict__ w) {
    int i = blockIdx.x * 256 + threadIdx.x;          // over O*C*KK = 36864
    if (i < O_ * C_ * KK) {
        int o = i / (C_ * KK);
        int r = i - o * (C_ * KK);
        int c = r / KK;
        int k = r - c * KK;
        g_wT[(k * C_ + c) * O_ + o] = w[i];
    }
}

__global__ void prep_x4(const float* __restrict__ x) {
    int i = blockIdx.x * 256 + threadIdx.x;          // over B*C*HW
    if (i < B_ * C_ * HW_) {
        int col = i & (W_ - 1);
        int y   = (i >> 7) & (H_ - 1);
        float a = x[i];
        float b = (col < W_ - 1) ? x[i + 1] : a;     // clamped; weight 0 there
        float c, d;
        if (y < H_ - 1) {
            c = x[i + W_];
            d = (col < W_ - 1) ? x[i + W_ + 1] : c;
        } else { c = a; d = b; }                     // weight 0 on bottom row pair
        g_x4[i] = make_float4(a, b, c, d);
    }
}

// ---------------- main kernel ----------------
// 512 blocks (batch*row), 256 threads:
//   warps 0-3 = consumers (GEMM), warps 4-7 = producers (gather + weight stage)
// smem: vtile[2][64][128] f32 (2*32KB) + wslab[2][64][64] f32 (2*16KB) = 96 KB
#define VT_FLOATS (C_ * W_)     // 8192
#define WS_FLOATS (C_ * O_)     // 4096
#define SMEM_BYTES ((2 * VT_FLOATS + 2 * WS_FLOATS) * 4)

#define PACK2(d, s)     asm("mov.b64 %0, {%1, %1};" : "=l"(d) : "r"(__float_as_uint(s)))
#define FMA2(a, w, v)   asm("fma.rn.f32x2 %0, %1, %2, %0;" : "+l"(a) : "l"(w), "l"(v))
#define UNPK(lo, hi, a) asm("mov.b64 {%0, %1}, %2;" : "=r"(lo), "=r"(hi) : "l"(a))

// named barriers: 1+s = "stage s full", 3+s = "stage s empty"; count = 256
#define BSYNC(id)   asm volatile("bar.sync %0, 256;"   :: "r"(id) : "memory")
#define BARRIVE(id) asm volatile("bar.arrive %0, 256;" :: "r"(id) : "memory")

__global__ __launch_bounds__(256, 2)
void dconv_main(const float* __restrict__ offset,
                const float* __restrict__ bias,
                float* __restrict__ out) {
    extern __shared__ float sm[];
    float* vtile = sm;                       // [2][64][128]
    float* wslab = sm + 2 * VT_FLOATS;       // [2][64][64]

    const int tid   = threadIdx.x;
    const int batch = blockIdx.x >> 7;
    const int ho    = blockIdx.x & 127;

    if (tid >= 128) {
        // ================= PRODUCERS (warps 4-7) =================
        const int p = tid - 128;             // pixel 0..127
        const float4* xb4  = g_x4 + batch * C_ * HW_;
        const float*  offb = offset + (batch * 2 * KK) * HW_ + ho * W_ + p;

        float offy[KK], offx[KK];
        #pragma unroll
        for (int k = 0; k < KK; k++) {
            offy[k] = __ldg(offb + (2 * k) * HW_);
            offx[k] = __ldg(offb + (2 * k + 1) * HW_);
        }

        for (int k = 0; k < KK; k++) {
            const int s = k & 1;
            if (k >= 2) BSYNC(3 + s);        // wait stage empty

            // stage this tap's weight slab (16KB, coalesced float4)
            {
                const float4* src = (const float4*)(g_wT + k * WS_FLOATS);
                float4* dst = (float4*)(wslab + s * WS_FLOATS);
                #pragma unroll
                for (int j = 0; j < 8; j++) dst[p + j * 128] = src[p + j * 128];
            }

            // bilinear corner math (once per pixel/tap)
            const int ki = k / 3, kj = k - ki * 3;
            const float py  = offy[k] + (float)(ki - 1 + ho);
            const float pxx = offx[k] + (float)(kj - 1 + p);
            const float y0f = floorf(py), x0f = floorf(pxx);
            const float ly = py - y0f,  lx = pxx - x0f;
            const float hy = 1.f - ly,  hx = 1.f - lx;
            const int y0 = (int)y0f, x0 = (int)x0f;

            // fold y-boundary into (w_top, w_bot) at row-pair ybase
            int ybase; float w_top, w_bot;
            if (y0 >= 0) {
                ybase = min(y0, H_ - 1);
                w_top = (y0 < H_)     ? hy : 0.f;
                w_bot = (y0 < H_ - 1) ? ly : 0.f;
            } else {
                ybase = 0;
                w_top = (y0 == -1) ? ly : 0.f;   // pair.top = row 0 = the y1 tap
                w_bot = 0.f;
            }
            // fold x-boundary into (wa, wb) at col-pair bx
            float wa, wb;
            if (x0 >= 0 && x0 < W_) { wa = hx; wb = (x0 < W_ - 1) ? lx : 0.f; }
            else if (x0 == -1)      { wa = lx; wb = 0.f; }
            else                    { wa = 0.f; wb = 0.f; }
            const int bx = min(max(x0, 0), W_ - 1);

            const float u0 = w_top * wa, u1 = w_top * wb;
            const float u2 = w_bot * wa, u3 = w_bot * wb;

            const float4* q = xb4 + ybase * W_ + bx;
            float* vt = vtile + s * VT_FLOATS + p;
            #pragma unroll 8
            for (int c = 0; c < C_; c++) {
                const float4 t = __ldg(q + c * HW_);   // ONE gather per (c,px)
                vt[c * W_] = u0 * t.x + u1 * t.y + u2 * t.z + u3 * t.w;
            }

            BARRIVE(1 + s);                  // stage full
        }
    } else {
        // ================= CONSUMERS (warps 0-3) =================
        // warp tile: 64 px x 32 o ; lane = (pxg 0-15, oh 0-1) -> 4 px x 16 o
        const int wc   = tid >> 5;
        const int lane = tid & 31;
        const int pxg  = lane & 15;
        const int oh   = lane >> 4;
        const int px0   = (wc & 1) * 64 + pxg * 4;
        const int obase = (wc >> 1) * 32 + oh * 16;

        unsigned long long acc[8][4];        // [o-pair][px]
        #pragma unroll
        for (int j = 0; j < 8; j++)
            #pragma unroll
            for (int p = 0; p < 4; p++) acc[j][p] = 0ULL;

        for (int k = 0; k < KK; k++) {
            const int s = k & 1;
            BSYNC(1 + s);                    // wait stage full

            const float* vt = vtile + s * VT_FLOATS + px0;
            const float* ws = wslab + s * WS_FLOATS + obase;
            #pragma unroll 2
            for (int c = 0; c < C_; c++) {
                const float4 v4 = *(const float4*)(vt + c * W_);
                // row stride = 64 floats per c (FIX: was 32 floats in R6)
                const ulonglong2* wr = (const ulonglong2*)(ws + c * O_);
                const ulonglong2 wA = wr[0], wB = wr[1], wC = wr[2], wD = wr[3];

                unsigned long long vv0, vv1, vv2, vv3;
                PACK2(vv0, v4.x); PACK2(vv1, v4.y);
                PACK2(vv2, v4.z); PACK2(vv3, v4.w);

                FMA2(acc[0][0], wA.x, vv0); FMA2(acc[0][1], wA.x, vv1);
                FMA2(acc[0][2], wA.x, vv2); FMA2(acc[0][3], wA.x, vv3);
                FMA2(acc[1][0], wA.y, vv0); FMA2(acc[1][1], wA.y, vv1);
                FMA2(acc[1][2], wA.y, vv2); FMA2(acc[1][3], wA.y, vv3);
                FMA2(acc[2][0], wB.x, vv0); FMA2(acc[2][1], wB.x, vv1);
                FMA2(acc[2][2], wB.x, vv2); FMA2(acc[2][3], wB.x, vv3);
                FMA2(acc[3][0], wB.y, vv0); FMA2(acc[3][1], wB.y, vv1);
                FMA2(acc[3][2], wB.y, vv2); FMA2(acc[3][3], wB.y, vv3);
                FMA2(acc[4][0], wC.x, vv0); FMA2(acc[4][1], wC.x, vv1);
                FMA2(acc[4][2], wC.x, vv2); FMA2(acc[4][3], wC.x, vv3);
                FMA2(acc[5][0], wC.y, vv0); FMA2(acc[5][1], wC.y, vv1);
                FMA2(acc[5][2], wC.y, vv2); FMA2(acc[5][3], wC.y, vv3);
                FMA2(acc[6][0], wD.x, vv0); FMA2(acc[6][1], wD.x, vv1);
                FMA2(acc[6][2], wD.x, vv2); FMA2(acc[6][3], wD.x, vv3);
                FMA2(acc[7][0], wD.y, vv0); FMA2(acc[7][1], wD.y, vv1);
                FMA2(acc[7][2], wD.y, vv2); FMA2(acc[7][3], wD.y, vv3);
            }

            BARRIVE(3 + s);                  // stage empty
        }

        // epilogue: unpack, +bias, float4 stores (4 px contiguous per o)
        float* ob = out + (batch * O_) * HW_ + ho * W_ + px0;
        #pragma unroll
        for (int j = 0; j < 8; j++) {
            const int o = obase + 2 * j;
            const float b0 = __ldg(bias + o);
            const float b1 = __ldg(bias + o + 1);
            unsigned int l0, h0, l1, h1, l2, h2, l3, h3;
            UNPK(l0, h0, acc[j][0]);
            UNPK(l1, h1, acc[j][1]);
            UNPK(l2, h2, acc[j][2]);
            UNPK(l3, h3, acc[j][3]);
            float4 r0 = make_float4(__uint_as_float(l0) + b0, __uint_as_float(l1) + b0,
                                    __uint_as_float(l2) + b0, __uint_as_float(l3) + b0);
            float4 r1 = make_float4(__uint_as_float(h0) + b1, __uint_as_float(h1) + b1,
                                    __uint_as_float(h2) + b1, __uint_as_float(h3) + b1);
            *(float4*)(ob + o * HW_)       = r0;
            *(float4*)(ob + (o + 1) * HW_) = r1;
        }
    }
}

extern "C" void kernel_launch(void* const* d_in, const int* in_sizes, int n_in,
                              void* d_out, int out_size) {
    const float* x      = (const float*)d_in[0];
    const float* offset = (const float*)d_in[1];
    const float* weight = (const float*)d_in[2];
    const float* bias   = (const float*)d_in[3];
    float* out = (float*)d_out;

    cudaFuncSetAttribute(dconv_main,
                         cudaFuncAttributeMaxDynamicSharedMemorySize, SMEM_BYTES);

    prep_w<<<(O_ * C_ * KK + 255) / 256, 256>>>(weight);
    prep_x4<<<(B_ * C_ * HW_ + 255) / 256, 256>>>(x);
    dconv_main<<<B_ * H_, 256, SMEM_BYTES>>>(offset, bias, out);
}